// round 6
// baseline (speedup 1.0000x reference)
#include <cuda_runtime.h>

// LengthRegulator: predictor in the reference is dead code (overridden by
// target_durations). Real work: per-batch cumsum + upper_bound gather-expand.

#define BB 8
#define TT 1024
#define DD 1024
#define FF 8192          // MAX_FRAMES = T * DMAX
#define WV 8             // frames per group (one int16x8 tok vector = 16 B)
#define NGRP (BB * FF / WV)   // 8192 groups
#define GRID 592         // 4 blocks x 148 SMs, persistent

// token index per (b, frame) as int16; -1 means invalid (zero-fill). 128 KB.
__device__ short g_tok[BB * FF];

// One block per batch row: scan durations, binary-search all 8192 frames,
// and emit the durations tail of the output.
__global__ void lr_prep_kernel(const int* __restrict__ dur,
                               float* __restrict__ out_tail,
                               int write_tail) {
    const int b = blockIdx.x;
    const int t = threadIdx.x;

    __shared__ int s[TT];
    const int d = dur[b * TT + t];
    s[t] = d;
    __syncthreads();

    // Hillis–Steele inclusive scan over 1024 elements (10 steps).
    #pragma unroll
    for (int off = 1; off < TT; off <<= 1) {
        const int v = (t >= off) ? s[t - off] : 0;
        __syncthreads();
        s[t] += v;
        __syncthreads();
    }
    const int total = s[TT - 1];

    // Each thread resolves 8 frames: upper_bound(cum, f) -> first i with cum[i] > f.
    #pragma unroll
    for (int k = 0; k < FF / TT; ++k) {
        const int f = t + k * TT;
        int tok;
        if (f >= total) {
            tok = -1;
        } else {
            int lo = 0, hi = TT;
            while (lo < hi) {              // run to convergence (1025 candidates)
                const int mid = (lo + hi) >> 1;
                if (s[mid] > f) hi = mid; else lo = mid + 1;
            }
            tok = lo;                      // f < total guarantees lo <= TT-1
        }
        g_tok[b * FF + f] = (short)tok;
    }

    if (write_tail) {
        out_tail[b * TT + t] = (float)d;   // durations, numeric cast to f32 output
    }
}

__device__ __forceinline__ int unpack_tok(const int4& q, int i) {
    const int w = (i < 2) ? q.x : (i < 4) ? q.y : (i < 6) ? q.z : q.w;
    return (int)(short)((i & 1) ? (w >> 16) : (w & 0xFFFF));   // sign-extends -1
}

// Persistent grid-stride expand: each iteration handles one 8-frame group.
// Tok vector for the NEXT iteration is prefetched (one LDG.128 broadcast)
// before the current stores, so the tok->address->load chain is hidden.
__global__ void __launch_bounds__(DD / 4)
lr_expand_kernel(const float* __restrict__ x, float* __restrict__ out) {
    const int c = threadIdx.x;            // 0..255, one float4 column
    const int4* __restrict__ tokv = reinterpret_cast<const int4*>(g_tok);

    int g = blockIdx.x;
    int4 tq = tokv[g];                    // toks for first group

    while (g < NGRP) {
        const int b = g >> 10;            // 1024 groups per batch row (FF/WV)
        const float4* xb = reinterpret_cast<const float4*>(x)
                         + (size_t)b * TT * (DD / 4);

        // 8 independent LDG.128 in flight (explicit register buffer).
        float4 v[WV];
        #pragma unroll
        for (int i = 0; i < WV; ++i) {
            const int tk = unpack_tok(tq, i);
            if (tk >= 0)
                v[i] = __ldg(&xb[(size_t)tk * (DD / 4) + c]);
            else
                v[i] = make_float4(0.f, 0.f, 0.f, 0.f);
        }

        // Prefetch next group's toks while current x-loads are in flight.
        const int gn = g + GRID;
        int4 tqn = make_int4(-1, -1, -1, -1);
        if (gn < NGRP) tqn = tokv[gn];

        float4* dst = reinterpret_cast<float4*>(out)
                    + (size_t)g * WV * (DD / 4) + c;
        #pragma unroll
        for (int i = 0; i < WV; ++i)
            __stcs(&dst[(size_t)i * (DD / 4)], v[i]);   // streaming stores

        tq = tqn;
        g  = gn;
    }
}

extern "C" void kernel_launch(void* const* d_in, const int* in_sizes, int n_in,
                              void* d_out, int out_size) {
    const float* x   = (const float*)d_in[0];   // [B, T, D] f32
    const int*   dur = (const int*)d_in[1];     // [B, T] i32
    float* out = (float*)d_out;

    const long long padded_elems = (long long)BB * FF * DD;   // 67,108,864
    const int write_tail = (out_size >= padded_elems + BB * TT) ? 1 : 0;

    lr_prep_kernel<<<BB, TT>>>(dur, out + padded_elems, write_tail);
    lr_expand_kernel<<<GRID, DD / 4>>>(x, out);
}

// round 7
// speedup vs baseline: 1.0763x; 1.0763x over previous
#include <cuda_runtime.h>

// LengthRegulator: predictor in the reference is dead code (overridden by
// target_durations). Real work: per-batch cumsum + upper_bound gather-expand.

#define BB 8
#define TT 1024
#define DD 1024
#define FF 8192          // MAX_FRAMES = T * DMAX
#define WV 8             // frames per block group (one int16x8 tok vector)

// token index per (b, frame) as int16; -1 means invalid (zero-fill). 128 KB.
__device__ short g_tok[BB * FF];

// One block per batch row: scan durations, binary-search all 8192 frames,
// and emit the durations tail of the output.
__global__ void lr_prep_kernel(const int* __restrict__ dur,
                               float* __restrict__ out_tail,
                               int write_tail) {
    const int b = blockIdx.x;
    const int t = threadIdx.x;

    __shared__ int s[TT];
    const int d = dur[b * TT + t];
    s[t] = d;
    __syncthreads();

    // Hillis–Steele inclusive scan over 1024 elements (10 steps).
    #pragma unroll
    for (int off = 1; off < TT; off <<= 1) {
        const int v = (t >= off) ? s[t - off] : 0;
        __syncthreads();
        s[t] += v;
        __syncthreads();
    }
    const int total = s[TT - 1];

    // Each thread resolves 8 frames: upper_bound(cum, f) -> first i with cum[i] > f.
    #pragma unroll
    for (int k = 0; k < FF / TT; ++k) {
        const int f = t + k * TT;
        int tok;
        if (f >= total) {
            tok = -1;
        } else {
            int lo = 0, hi = TT;
            while (lo < hi) {              // run to convergence (1025 candidates)
                const int mid = (lo + hi) >> 1;
                if (s[mid] > f) hi = mid; else lo = mid + 1;
            }
            tok = lo;                      // f < total guarantees lo <= TT-1
        }
        g_tok[b * FF + f] = (short)tok;
    }

    if (write_tail) {
        out_tail[b * TT + t] = (float)d;   // durations, numeric cast to f32 output
    }
}

__device__ __forceinline__ int unpack_tok(const int4& q, int i) {
    const int w = (i < 2) ? q.x : (i < 4) ? q.y : (i < 6) ? q.z : q.w;
    return (int)(short)((i & 1) ? (w >> 16) : (w & 0xFFFF));   // sign-extends -1
}

// One block per 8-frame group. Tok vector fetched with one uniform LDG.128.
// asm volatile forces SASS order: 8 batched LDG.128 (true MLP=8), then FSEL
// zero-fix for invalid frames, then 8 streaming STG.128.
__global__ void __launch_bounds__(DD / 4)
lr_expand_kernel(const float* __restrict__ x, float* __restrict__ out) {
    const int g = blockIdx.x;             // group id: b*1024 + group-in-row
    const int b = g >> 10;                // FF/WV = 1024 groups per batch row
    const int c = threadIdx.x;            // 0..255, one float4 column each

    const int4 tq = reinterpret_cast<const int4*>(g_tok)[g];   // uniform

    const float4* xb = reinterpret_cast<const float4*>(x)
                     + (size_t)b * TT * (DD / 4) + c;

    int   tk[WV];
    float vx[WV], vy[WV], vz[WV], vw[WV];

    // Batched loads: invalid frames clamp to row 0 (cheap L2 hit), zeroed below.
    #pragma unroll
    for (int i = 0; i < WV; ++i) {
        tk[i] = unpack_tok(tq, i);
        const float4* p = xb + (size_t)max(tk[i], 0) * (DD / 4);
        asm volatile("ld.global.nc.v4.f32 {%0,%1,%2,%3}, [%4];"
                     : "=f"(vx[i]), "=f"(vy[i]), "=f"(vz[i]), "=f"(vw[i])
                     : "l"(p));
    }

    #pragma unroll
    for (int i = 0; i < WV; ++i) {
        if (tk[i] < 0) { vx[i] = 0.f; vy[i] = 0.f; vz[i] = 0.f; vw[i] = 0.f; }
    }

    float4* dst = reinterpret_cast<float4*>(out)
                + (size_t)g * WV * (DD / 4) + c;
    #pragma unroll
    for (int i = 0; i < WV; ++i) {
        asm volatile("st.global.cs.v4.f32 [%0], {%1,%2,%3,%4};"
                     :: "l"(dst + (size_t)i * (DD / 4)),
                        "f"(vx[i]), "f"(vy[i]), "f"(vz[i]), "f"(vw[i])
                     : "memory");
    }
}

extern "C" void kernel_launch(void* const* d_in, const int* in_sizes, int n_in,
                              void* d_out, int out_size) {
    const float* x   = (const float*)d_in[0];   // [B, T, D] f32
    const int*   dur = (const int*)d_in[1];     // [B, T] i32
    float* out = (float*)d_out;

    const long long padded_elems = (long long)BB * FF * DD;   // 67,108,864
    const int write_tail = (out_size >= padded_elems + BB * TT) ? 1 : 0;

    lr_prep_kernel<<<BB, TT>>>(dur, out + padded_elems, write_tail);
    lr_expand_kernel<<<(BB * FF) / WV, DD / 4>>>(x, out);
}

// round 9
// speedup vs baseline: 1.0825x; 1.0058x over previous
#include <cuda_runtime.h>

// LengthRegulator: predictor in the reference is dead code (overridden by
// target_durations). Real work: per-batch cumsum + upper_bound gather-expand.
// Expand is at the HBM write-stream ceiling (~5.6 TB/s of stores); this round
// removes the prep+launch serialization gap via PDL.

#define BB 8
#define TT 1024
#define DD 1024
#define FF 8192          // MAX_FRAMES = T * DMAX
#define WV 8             // frames per block group (one int16x8 tok vector)

// token index per (b, frame) as int16; -1 means invalid (zero-fill). 128 KB.
__device__ short g_tok[BB * FF];

// One block per batch row: scan durations, binary-search all 8192 frames,
// trigger the dependent expand launch, then emit the durations tail.
__global__ void lr_prep_kernel(const int* __restrict__ dur,
                               float* __restrict__ out_tail,
                               int write_tail) {
    const int b = blockIdx.x;
    const int t = threadIdx.x;

    __shared__ int s[TT];
    const int d = dur[b * TT + t];
    s[t] = d;
    __syncthreads();

    // Hillis–Steele inclusive scan over 1024 elements (10 steps).
    #pragma unroll
    for (int off = 1; off < TT; off <<= 1) {
        const int v = (t >= off) ? s[t - off] : 0;
        __syncthreads();
        s[t] += v;
        __syncthreads();
    }
    const int total = s[TT - 1];

    // Each thread resolves 8 frames: upper_bound(cum, f) -> first i with cum[i] > f.
    #pragma unroll
    for (int k = 0; k < FF / TT; ++k) {
        const int f = t + k * TT;
        int tok;
        if (f >= total) {
            tok = -1;
        } else {
            int lo = 0, hi = TT;
            while (lo < hi) {              // run to convergence (1025 candidates)
                const int mid = (lo + hi) >> 1;
                if (s[mid] > f) hi = mid; else lo = mid + 1;
            }
            tok = lo;                      // f < total guarantees lo <= TT-1
        }
        g_tok[b * FF + f] = (short)tok;
    }

    // g_tok for this block is written: allow the dependent expand grid to fly.
    cudaTriggerProgrammaticLaunchCompletion();

    if (write_tail) {
        out_tail[b * TT + t] = (float)d;   // durations, numeric cast to f32 output
    }
}

__device__ __forceinline__ int unpack_tok(const int4& q, int i) {
    const int w = (i < 2) ? q.x : (i < 4) ? q.y : (i < 6) ? q.z : q.w;
    return (int)(short)((i & 1) ? (w >> 16) : (w & 0xFFFF));   // sign-extends -1
}

// One block per 8-frame group. PDL: setup overlaps the tail of prep; the grid
// dependency sync fences g_tok visibility. Then one uniform int4 tok fetch,
// 8 batched LDG.128, zero-fix, 8 streaming STG.128.
__global__ void __launch_bounds__(DD / 4)
lr_expand_kernel(const float* __restrict__ x, float* __restrict__ out) {
    const int g = blockIdx.x;             // group id: b*1024 + group-in-row
    const int b = g >> 10;                // FF/WV = 1024 groups per batch row
    const int c = threadIdx.x;            // 0..255, one float4 column each

    const float4* xb = reinterpret_cast<const float4*>(x)
                     + (size_t)b * TT * (DD / 4) + c;
    float4* dst = reinterpret_cast<float4*>(out)
                + (size_t)g * WV * (DD / 4) + c;

    cudaGridDependencySynchronize();      // prep's g_tok writes now visible

    const int4 tq = reinterpret_cast<const int4*>(g_tok)[g];   // uniform

    int   tk[WV];
    float vx[WV], vy[WV], vz[WV], vw[WV];

    // Batched loads: invalid frames clamp to row 0 (cheap L2 hit), zeroed below.
    #pragma unroll
    for (int i = 0; i < WV; ++i) {
        tk[i] = unpack_tok(tq, i);
        const float4* p = xb + (size_t)max(tk[i], 0) * (DD / 4);
        asm volatile("ld.global.nc.v4.f32 {%0,%1,%2,%3}, [%4];"
                     : "=f"(vx[i]), "=f"(vy[i]), "=f"(vz[i]), "=f"(vw[i])
                     : "l"(p));
    }

    #pragma unroll
    for (int i = 0; i < WV; ++i) {
        if (tk[i] < 0) { vx[i] = 0.f; vy[i] = 0.f; vz[i] = 0.f; vw[i] = 0.f; }
    }

    #pragma unroll
    for (int i = 0; i < WV; ++i) {
        asm volatile("st.global.cs.v4.f32 [%0], {%1,%2,%3,%4};"
                     :: "l"(dst + (size_t)i * (DD / 4)),
                        "f"(vx[i]), "f"(vy[i]), "f"(vz[i]), "f"(vw[i])
                     : "memory");
    }
}

extern "C" void kernel_launch(void* const* d_in, const int* in_sizes, int n_in,
                              void* d_out, int out_size) {
    const float* x   = (const float*)d_in[0];   // [B, T, D] f32
    const int*   dur = (const int*)d_in[1];     // [B, T] i32
    float* out = (float*)d_out;

    const long long padded_elems = (long long)BB * FF * DD;   // 67,108,864
    const int write_tail = (out_size >= padded_elems + BB * TT) ? 1 : 0;

    lr_prep_kernel<<<BB, TT>>>(dur, out + padded_elems, write_tail);

    // Expand launched as a programmatic dependent of prep (overlapped launch).
    cudaLaunchConfig_t cfg = {};
    cfg.gridDim  = dim3((BB * FF) / WV);
    cfg.blockDim = dim3(DD / 4);
    cfg.dynamicSmemBytes = 0;
    cfg.stream = 0;                        // same (legacy default) stream as prep
    cudaLaunchAttribute attr[1];
    attr[0].id = cudaLaunchAttributeProgrammaticStreamSerialization;
    attr[0].val.programmaticStreamSerializationAllowed = 1;
    cfg.attrs = attr;
    cfg.numAttrs = 1;
    cudaLaunchKernelEx(&cfg, lr_expand_kernel, x, out);
}

// round 10
// speedup vs baseline: 1.1555x; 1.0674x over previous
#include <cuda_runtime.h>

// LengthRegulator, fully fused: each block recomputes its row's duration
// cumsum (cheap shuffle scan in otherwise-idle issue slots), binary-searches
// its 8 frames, then does the bandwidth-bound gather-expand. One kernel,
// no scratch, no inter-kernel gap. Predictor in the reference is dead code.

#define BB 8
#define TT 1024
#define DD 1024
#define FF 8192          // MAX_FRAMES = T * DMAX
#define WV 8             // frames per block

__global__ void __launch_bounds__(DD / 4)
lr_fused_kernel(const float* __restrict__ x,
                const int*   __restrict__ dur,
                float* __restrict__ out,
                int write_tail) {
    const int g    = blockIdx.x;          // group id: b*1024 + group-in-row
    const int b    = g >> 10;             // FF/WV = 1024 groups per batch row
    const int c    = threadIdx.x;         // 0..255
    const int lane = c & 31;
    const int wid  = c >> 5;              // 8 warps

    __shared__ int s[TT];                 // inclusive cumsum of this row
    __shared__ int wsum[8];
    __shared__ int stok[WV];

    // ---- row cumsum: int4 load + warp/block shuffle scan (2 barriers) ----
    const int4 dv = reinterpret_cast<const int4*>(dur)[b * (TT / 4) + c];
    const int tsum = dv.x + dv.y + dv.z + dv.w;

    int incl = tsum;                      // warp-inclusive scan of thread sums
    #pragma unroll
    for (int off = 1; off < 32; off <<= 1) {
        const int n = __shfl_up_sync(0xFFFFFFFF, incl, off);
        if (lane >= off) incl += n;
    }
    if (lane == 31) wsum[wid] = incl;
    __syncthreads();
    if (c < 8) {                          // exclusive scan of 8 warp totals
        int w = wsum[c], e = 0;
        #pragma unroll
        for (int j = 0; j < 8; ++j) { int v = __shfl_sync(0xFF, w, j); if (j < c) e += v; }
        wsum[c] = e;
    }
    __syncthreads();
    const int base = wsum[wid] + (incl - tsum);   // exclusive prefix, this thread
    s[c * 4 + 0] = base + dv.x;
    s[c * 4 + 1] = base + dv.x + dv.y;
    s[c * 4 + 2] = base + dv.x + dv.y + dv.z;
    s[c * 4 + 3] = base + tsum;

    // durations tail: 32 blocks (all with b==0, dur row 0 in L2) cover B*T.
    if (write_tail && g < 32)
        out[(size_t)BB * FF * DD + g * 256 + c] =
            (float)__ldg(&dur[g * 256 + c]);
    __syncthreads();

    // ---- upper_bound for this block's 8 frames (threads 0..7) ----
    const int total = s[TT - 1];
    if (c < WV) {
        const int f = (g & 1023) * WV + c;
        int tok = -1;
        if (f < total) {
            int lo = 0, hi = TT;
            while (lo < hi) {             // run to convergence
                const int mid = (lo + hi) >> 1;
                if (s[mid] > f) hi = mid; else lo = mid + 1;
            }
            tok = lo;                     // f < total guarantees lo <= TT-1
        }
        stok[c] = tok;
    }
    __syncthreads();

    // ---- gather + streaming store body (unchanged from best kernel) ----
    const float4* xb = reinterpret_cast<const float4*>(x)
                     + (size_t)b * TT * (DD / 4) + c;
    float4* dst = reinterpret_cast<float4*>(out)
                + (size_t)g * WV * (DD / 4) + c;

    int   tk[WV];
    float vx[WV], vy[WV], vz[WV], vw[WV];

    #pragma unroll
    for (int i = 0; i < WV; ++i) {
        tk[i] = stok[i];                  // LDS broadcast
        const float4* p = xb + (size_t)max(tk[i], 0) * (DD / 4);
        asm volatile("ld.global.nc.v4.f32 {%0,%1,%2,%3}, [%4];"
                     : "=f"(vx[i]), "=f"(vy[i]), "=f"(vz[i]), "=f"(vw[i])
                     : "l"(p));
    }
    #pragma unroll
    for (int i = 0; i < WV; ++i) {
        if (tk[i] < 0) { vx[i] = 0.f; vy[i] = 0.f; vz[i] = 0.f; vw[i] = 0.f; }
    }
    #pragma unroll
    for (int i = 0; i < WV; ++i) {
        asm volatile("st.global.cs.v4.f32 [%0], {%1,%2,%3,%4};"
                     :: "l"(dst + (size_t)i * (DD / 4)),
                        "f"(vx[i]), "f"(vy[i]), "f"(vz[i]), "f"(vw[i])
                     : "memory");
    }
}

extern "C" void kernel_launch(void* const* d_in, const int* in_sizes, int n_in,
                              void* d_out, int out_size) {
    const float* x   = (const float*)d_in[0];   // [B, T, D] f32
    const int*   dur = (const int*)d_in[1];     // [B, T] i32
    float* out = (float*)d_out;

    const long long padded_elems = (long long)BB * FF * DD;   // 67,108,864
    const int write_tail = (out_size >= padded_elems + BB * TT) ? 1 : 0;

    lr_fused_kernel<<<(BB * FF) / WV, DD / 4>>>(x, dur, out, write_tail);
}

// round 12
// speedup vs baseline: 1.1652x; 1.0083x over previous
#include <cuda_runtime.h>

// LengthRegulator, fused single kernel. Each block: recompute row cumsum
// (shuffle scan in idle issue slots), binary-search its 16 frames, then two
// 8-frame gather/stream-store waves. Invalid frames (~56%!) skip the load.
// Predictor in the reference is dead code.

#define BB 8
#define TT 1024
#define DD 1024
#define FF 8192          // MAX_FRAMES = T * DMAX
#define WVB 16           // frames per block
#define WV 8             // frames per inner wave

__global__ void __launch_bounds__(DD / 4)
lr_fused_kernel(const float* __restrict__ x,
                const int*   __restrict__ dur,
                float* __restrict__ out,
                int write_tail) {
    const int g    = blockIdx.x;          // group id: b*512 + group-in-row
    const int b    = g >> 9;              // FF/WVB = 512 groups per batch row
    const int c    = threadIdx.x;         // 0..255
    const int lane = c & 31;
    const int wid  = c >> 5;              // 8 warps

    __shared__ int s[TT];                 // inclusive cumsum of this row
    __shared__ int wsum[8];
    __shared__ int stok[WVB];

    // ---- row cumsum: int4 load + warp/block shuffle scan ----
    const int4 dv = reinterpret_cast<const int4*>(dur)[b * (TT / 4) + c];
    const int tsum = dv.x + dv.y + dv.z + dv.w;

    int incl = tsum;
    #pragma unroll
    for (int off = 1; off < 32; off <<= 1) {
        const int n = __shfl_up_sync(0xFFFFFFFF, incl, off);
        if (lane >= off) incl += n;
    }
    if (lane == 31) wsum[wid] = incl;
    __syncthreads();
    if (c < 8) {                          // exclusive scan of 8 warp totals
        int w = wsum[c], e = 0;
        #pragma unroll
        for (int j = 0; j < 8; ++j) { int v = __shfl_sync(0xFF, w, j); if (j < c) e += v; }
        wsum[c] = e;
    }
    __syncthreads();
    const int base = wsum[wid] + (incl - tsum);
    s[c * 4 + 0] = base + dv.x;
    s[c * 4 + 1] = base + dv.x + dv.y;
    s[c * 4 + 2] = base + dv.x + dv.y + dv.z;
    s[c * 4 + 3] = base + tsum;

    // durations tail: 32 blocks cover B*T (=8192) ints -> f32.
    if (write_tail && g < 32)
        out[(size_t)BB * FF * DD + g * 256 + c] =
            (float)__ldg(&dur[g * 256 + c]);
    __syncthreads();

    // ---- upper_bound for this block's 16 frames (threads 0..15) ----
    const int total = s[TT - 1];
    if (c < WVB) {
        const int f = (g & 511) * WVB + c;
        int tok = -1;
        if (f < total) {
            int lo = 0, hi = TT;
            while (lo < hi) {
                const int mid = (lo + hi) >> 1;
                if (s[mid] > f) hi = mid; else lo = mid + 1;
            }
            tok = lo;                     // f < total guarantees lo <= TT-1
        }
        stok[c] = tok;
    }
    __syncthreads();

    // ---- two 8-frame gather/store waves; invalid frames skip the load ----
    const float4* xb = reinterpret_cast<const float4*>(x)
                     + (size_t)b * TT * (DD / 4) + c;
    float4* dst = reinterpret_cast<float4*>(out)
                + (size_t)g * WVB * (DD / 4) + c;

    #pragma unroll
    for (int w = 0; w < WVB / WV; ++w) {
        int   tk[WV];
        float vx[WV], vy[WV], vz[WV], vw[WV];

        #pragma unroll
        for (int i = 0; i < WV; ++i) {
            tk[i] = stok[w * WV + i];     // LDS broadcast (block-uniform)
            vx[i] = 0.f; vy[i] = 0.f; vz[i] = 0.f; vw[i] = 0.f;
            if (tk[i] >= 0) {             // uniform branch: no divergence
                const float4* p = xb + (size_t)tk[i] * (DD / 4);
                asm volatile("ld.global.nc.v4.f32 {%0,%1,%2,%3}, [%4];"
                             : "=f"(vx[i]), "=f"(vy[i]), "=f"(vz[i]), "=f"(vw[i])
                             : "l"(p));
            }
        }
        #pragma unroll
        for (int i = 0; i < WV; ++i) {
            asm volatile("st.global.cs.v4.f32 [%0], {%1,%2,%3,%4};"
                         :: "l"(dst + (size_t)(w * WV + i) * (DD / 4)),
                            "f"(vx[i]), "f"(vy[i]), "f"(vz[i]), "f"(vw[i])
                         : "memory");
        }
    }
}

extern "C" void kernel_launch(void* const* d_in, const int* in_sizes, int n_in,
                              void* d_out, int out_size) {
    const float* x   = (const float*)d_in[0];   // [B, T, D] f32
    const int*   dur = (const int*)d_in[1];     // [B, T] i32
    float* out = (float*)d_out;

    const long long padded_elems = (long long)BB * FF * DD;   // 67,108,864
    const int write_tail = (out_size >= padded_elems + BB * TT) ? 1 : 0;

    lr_fused_kernel<<<(BB * FF) / WVB, DD / 4>>>(x, dur, out, write_tail);
}